// round 15
// baseline (speedup 1.0000x reference)
#include <cuda_runtime.h>
#include <cuda_fp16.h>
#include <math.h>

// Problem constants (fixed by the dataset)
#define NCAP 100000
#define ECAP 1600000
#define DIM  64
#define HID  128

// ---------------- scratch (device globals; no runtime allocation) ----------
static __device__ __align__(128) int   d_cnt[NCAP];
static __device__ __align__(128) int   d_rowptr[NCAP + 1];
static __device__ __align__(128) int   d_cursor[NCAP];
static __device__ __align__(128) int   d_bsum[256];
static __device__ __align__(128) int   d_col[ECAP];
static __device__ __align__(128) float d_dinv[NCAP];
static __device__ __align__(128) unsigned int d_xh[NCAP * 32]; // fp16x2 dinv*renorm(x)
static __device__ __align__(128) float d_agg1[NCAP * DIM];     // Ahat(x)
static __device__ __align__(128) unsigned int d_gh[NCAP * 32]; // fp16x2 dinv*(relu(..)@W2)

// ---------------- f32x2 packed math (Blackwell FFMA2) -----------------------
__device__ __forceinline__ unsigned long long pk2(float lo, float hi) {
    unsigned long long r;
    asm("mov.b64 %0, {%1, %2};" : "=l"(r) : "r"(__float_as_uint(lo)), "r"(__float_as_uint(hi)));
    return r;
}
__device__ __forceinline__ unsigned long long fma2(unsigned long long a,
                                                   unsigned long long b,
                                                   unsigned long long c) {
    unsigned long long d;
    asm("fma.rn.f32x2 %0, %1, %2, %3;" : "=l"(d) : "l"(a), "l"(b), "l"(c));
    return d;
}
__device__ __forceinline__ float2 upk2(unsigned long long v) {
    unsigned int lo, hi;
    asm("mov.b64 {%0, %1}, %2;" : "=r"(lo), "=r"(hi) : "l"(v));
    return make_float2(__uint_as_float(lo), __uint_as_float(hi));
}

// ---------------- cp.async helpers -------------------------------------------
__device__ __forceinline__ void cp_async16(void* sdst, const void* gsrc, bool valid) {
    unsigned saddr = (unsigned)__cvta_generic_to_shared(sdst);
    int sz = valid ? 16 : 0;     // src_size=0 -> zero-fill 16 bytes
    asm volatile("cp.async.cg.shared.global [%0], [%1], 16, %2;"
                 :: "r"(saddr), "l"(gsrc), "r"(sz));
}
#define CP_COMMIT()  asm volatile("cp.async.commit_group;" ::: "memory")
#define CP_WAIT1()   asm volatile("cp.async.wait_group 1;" ::: "memory")

// ---------------- zero degree counters ---------------------------------------
__global__ void zero_cnt_kernel(int n4) {
    int i = blockIdx.x * blockDim.x + threadIdx.x;
    if (i < n4) *(int4*)&d_cnt[i * 4] = make_int4(0, 0, 0, 0);
}

// ---------------- degree counting (int4) -------------------------------------
__global__ void count_deg_kernel(const int* __restrict__ dst, int E) {
    int i = blockIdx.x * blockDim.x + threadIdx.x;
    int e = i * 4;
    if (e + 3 < E) {
        int4 d = *(const int4*)(dst + e);
        atomicAdd(&d_cnt[d.x], 1);
        atomicAdd(&d_cnt[d.y], 1);
        atomicAdd(&d_cnt[d.z], 1);
        atomicAdd(&d_cnt[d.w], 1);
    } else {
        for (; e < E; e++) atomicAdd(&d_cnt[dst[e]], 1);
    }
}

// ---------------- prefix sum (chunked) ---------------------------------------
__global__ void scan_chunk_kernel(int n) {
    __shared__ int s[1024];
    int t = threadIdx.x;
    int i = blockIdx.x * 1024 + t;
    int v = (i < n) ? d_cnt[i] : 0;
    s[t] = v;
    __syncthreads();
    for (int off = 1; off < 1024; off <<= 1) {
        int add = (t >= off) ? s[t - off] : 0;
        __syncthreads();
        s[t] += add;
        __syncthreads();
    }
    if (i < n) d_rowptr[i] = s[t] - v;   // chunk-local exclusive
    if (t == 1023) d_bsum[blockIdx.x] = s[1023];
}

// finalize with inline bsum prefix: block c adds sum(d_bsum[0..c))
__global__ void finalize_rowptr_kernel(int n, int Etot) {
    __shared__ int s_off;
    int c = blockIdx.x, t = threadIdx.x;
    if (t < 32) {
        int s = 0;
        for (int j = t; j < c; j += 32) s += d_bsum[j];
        #pragma unroll
        for (int o = 16; o; o >>= 1) s += __shfl_xor_sync(0xffffffffu, s, o);
        if (t == 0) s_off = s;
    }
    __syncthreads();
    int i = c * 1024 + t;
    if (i < n) {
        int rp = d_rowptr[i] + s_off;
        d_rowptr[i] = rp;
        d_cursor[i] = rp;
        float deg = (float)(d_cnt[i] + 1);   // +1 self loop
        d_dinv[i] = rsqrtf(deg);
    }
    if (i == 0) d_rowptr[n] = Etot;
}

__global__ void fill_csr_kernel(const int* __restrict__ src,
                                const int* __restrict__ dst, int E) {
    int i = blockIdx.x * blockDim.x + threadIdx.x;
    int e = i * 4;
    if (e + 3 < E) {
        int4 d = *(const int4*)(dst + e);
        int4 s = *(const int4*)(src + e);
        d_col[atomicAdd(&d_cursor[d.x], 1)] = s.x;
        d_col[atomicAdd(&d_cursor[d.y], 1)] = s.y;
        d_col[atomicAdd(&d_cursor[d.z], 1)] = s.z;
        d_col[atomicAdd(&d_cursor[d.w], 1)] = s.w;
    } else {
        for (; e < E; e++) {
            int p = atomicAdd(&d_cursor[dst[e]], 1);
            d_col[p] = src[e];
        }
    }
}

// ---------------- renorm + premultiply by dinv, store fp16x2 -----------------
__global__ void renorm_premul_kernel(const float* __restrict__ emb, int n) {
    int gtid = blockIdx.x * blockDim.x + threadIdx.x;
    int row = gtid >> 5;
    int lane = gtid & 31;
    if (row >= n) return;
    float2 v = *(const float2*)(emb + (size_t)row * DIM + lane * 2);
    float ss = v.x * v.x + v.y * v.y;
    #pragma unroll
    for (int o = 16; o; o >>= 1) ss += __shfl_xor_sync(0xffffffffu, ss, o);
    float nrm = sqrtf(ss);
    float sc = fminf(1.0f, 1.0f / fmaxf(nrm, 1e-12f)) * d_dinv[row];
    __half2 h = __floats2half2_rn(v.x * sc, v.y * sc);
    d_xh[row * 32 + lane] = *(unsigned int*)&h;
}

// ---------------- aggregation: d_agg1 = Ahat(x) via premultiplied fp16 -------
__global__ void aggregate1_kernel(int n) {
    int gtid = blockIdx.x * blockDim.x + threadIdx.x;
    int r = gtid >> 5;
    int lane = gtid & 31;
    if (r >= n) return;
    int beg = d_rowptr[r], end = d_rowptr[r + 1];
    float2 acc = make_float2(0.f, 0.f);
    for (int e = beg; e < end; e++) {
        int s = d_col[e];
        unsigned int hb = d_xh[s * 32 + lane];
        float2 xs = __half22float2(*(__half2*)&hb);
        acc.x += xs.x;
        acc.y += xs.y;
    }
    unsigned int hr = d_xh[r * 32 + lane];
    float2 self = __half22float2(*(__half2*)&hr);
    float di = d_dinv[r];
    float2 o = make_float2(di * (acc.x + self.x),
                           di * (acc.y + self.y));
    *(float2*)(d_agg1 + (size_t)r * DIM + lane * 2) = o;
}

// ---------------- persistent fused GEMM1+GEMM2, cp.async A-prefetch ----------
// grid = 152 (1 block/SM), chunk-stride loop; weights loaded once per block;
// A tile double-buffered in smem, next chunk prefetched via cp.async.cg while
// current chunk computes. Inner loops identical to the validated R12/R14 code.
// stage 1: H = relu(A[128,64] @ W1[64,128] + b1) -> smem
// stage 2: G = fp16( dinv * (H @ W2[128,64]) )   -> d_gh
#define SA_STRIDE 68
#define SH_STRIDE 132
#define FUSED_SMEM_FLOATS (2 * 128 * SA_STRIDE + 64 * 128 + 128 * 64 + 128 * SH_STRIDE)
#define FUSED_SMEM_BYTES  (FUSED_SMEM_FLOATS * 4)
#define GEMM_GRID 152

__device__ __forceinline__ void prefetch_A(float* sbuf, int chunk, int n) {
    int rowBase = chunk << 7;
    #pragma unroll
    for (int t = threadIdx.x; t < 128 * 16; t += 256) {
        int r = t >> 4, k4 = t & 15;
        int gr = rowBase + r;
        bool valid = (gr < n);
        const float* g = d_agg1 + (size_t)(valid ? gr : 0) * DIM + k4 * 4;
        cp_async16(&sbuf[r * SA_STRIDE + k4 * 4], g, valid);
    }
    CP_COMMIT();
}

__global__ __launch_bounds__(256, 1)
void gemm_fused_kernel(const float* __restrict__ W1, const float* __restrict__ b1,
                       const float* __restrict__ W2, int M) {
    extern __shared__ float smem[];
    float* sA0 = smem;                          // [128][SA_STRIDE]
    float* sA1 = sA0 + 128 * SA_STRIDE;         // [128][SA_STRIDE]
    float* sW1 = sA1 + 128 * SA_STRIDE;         // paired layout [64][128]
    float* sW2 = sW1 + 64 * 128;                // [128][64]
    float* sH  = sW2 + 128 * 64;                // [128][SH_STRIDE]

    const int tid = threadIdx.x;
    const int tx = tid & 15, ty = tid >> 4;
    const int r0 = ty * 8;
    const int nch = (M + 127) >> 7;

    // --- prefetch first chunk into buf0 (overlaps weight loads) ---
    if ((int)blockIdx.x < nch) prefetch_A(sA0, blockIdx.x, M);
    else CP_COMMIT();

    // --- load W1 into pre-paired layout: pair (c, c+16) adjacent ---
    #pragma unroll
    for (int t = tid; t < 64 * 128; t += 256) {
        int k = t >> 7, c = t & 127;
        int txp = c & 15, m = c >> 4;
        int slot = (((m >> 1) * 16 + txp) << 1) + (m & 1);
        sW1[k * 128 + slot] = W1[t];
    }
    // --- load W2 (plain copy, float4) ---
    #pragma unroll
    for (int t = tid; t < 128 * 16; t += 256) {
        *(float4*)&sW2[t * 4] = *(const float4*)(W2 + t * 4);
    }

    // bias, pre-paired per thread (loop-invariant)
    float b1c[8];
    #pragma unroll
    for (int j = 0; j < 4; j++) {
        b1c[j * 2]     = b1[tx + 32 * j];
        b1c[j * 2 + 1] = b1[tx + 32 * j + 16];
    }

    int it = 0;
    for (int ch = blockIdx.x; ch < nch; ch += GEMM_GRID, it++) {
        float* sAc = (it & 1) ? sA1 : sA0;
        float* sAn = (it & 1) ? sA0 : sA1;
        int nxt = ch + GEMM_GRID;
        if (nxt < nch) prefetch_A(sAn, nxt, M);
        else CP_COMMIT();                  // keep group count aligned
        CP_WAIT1();                        // current buffer's group complete
        __syncthreads();                   // visibility across threads

        const int rowBase = ch << 7;

        // ---- stage 1: acc[i][j] = row r0+i, col pair (tx+32j, tx+32j+16) ----
        unsigned long long acc[8][4];
        #pragma unroll
        for (int i = 0; i < 8; i++)
            #pragma unroll
            for (int j = 0; j < 4; j++) acc[i][j] = 0ull;

        #pragma unroll 4
        for (int k = 0; k < 64; k++) {
            unsigned long long bd[4];
            #pragma unroll
            for (int j = 0; j < 4; j++)
                bd[j] = *(const unsigned long long*)&sW1[k * 128 + ((j * 16 + tx) << 1)];
            #pragma unroll
            for (int i = 0; i < 8; i++) {
                float a = sAc[(r0 + i) * SA_STRIDE + k];
                unsigned long long ad = pk2(a, a);
                #pragma unroll
                for (int j = 0; j < 4; j++)
                    acc[i][j] = fma2(ad, bd[j], acc[i][j]);
            }
        }
        __syncthreads();   // all stage-1 reads done; sH safe to overwrite

        // ---- bias + relu + write H to smem ----
        #pragma unroll
        for (int i = 0; i < 8; i++) {
            int rr = (r0 + i) * SH_STRIDE;
            #pragma unroll
            for (int j = 0; j < 4; j++) {
                float2 v = upk2(acc[i][j]);
                int c = tx + 32 * j;
                sH[rr + c]      = fmaxf(v.x + b1c[j * 2], 0.f);
                sH[rr + c + 16] = fmaxf(v.y + b1c[j * 2 + 1], 0.f);
            }
        }
        __syncthreads();

        // ---- stage 2: acc2[i][j] = row r0+i, cols (4tx+2j, 4tx+2j+1) ----
        unsigned long long acc2[8][2];
        #pragma unroll
        for (int i = 0; i < 8; i++) { acc2[i][0] = 0ull; acc2[i][1] = 0ull; }

        #pragma unroll 4
        for (int k = 0; k < 128; k++) {
            unsigned long long bd0 = *(const unsigned long long*)&sW2[k * 64 + 4 * tx];
            unsigned long long bd1 = *(const unsigned long long*)&sW2[k * 64 + 4 * tx + 2];
            #pragma unroll
            for (int i = 0; i < 8; i++) {
                float a = sH[(r0 + i) * SH_STRIDE + k];
                unsigned long long ad = pk2(a, a);
                acc2[i][0] = fma2(ad, bd0, acc2[i][0]);
                acc2[i][1] = fma2(ad, bd1, acc2[i][1]);
            }
        }

        // ---- epilogue: g' = fp16(dinv * G), coalesced uint2 stores ----
        #pragma unroll
        for (int i = 0; i < 8; i++) {
            int gr = rowBase + r0 + i;
            if (gr < M) {
                float dv = d_dinv[gr];
                float2 v0 = upk2(acc2[i][0]);
                float2 v1 = upk2(acc2[i][1]);
                __half2 h0 = __floats2half2_rn(dv * v0.x, dv * v0.y);
                __half2 h1 = __floats2half2_rn(dv * v1.x, dv * v1.y);
                uint2 o;
                o.x = *(unsigned int*)&h0;
                o.y = *(unsigned int*)&h1;
                *(uint2*)&d_gh[(size_t)gr * 32 + 2 * tx] = o;
            }
        }
        // next iteration's first touch of sH is after its post-stage-1 sync,
        // and the next prefetch targets the other sA buffer -> no extra sync.
    }
}

// ---------------- final: agg2 restricted to batch items + user dot ----------
// d_gh holds g' = fp16(dinv*g):  item = dinv[r]*(sum g'[s] + g'[r]) + b2
__global__ void final_kernel(const int* __restrict__ u,
                             const int* __restrict__ it,
                             const float* __restrict__ user_emb,
                             const float* __restrict__ b2,
                             float* __restrict__ out, int B) {
    int gtid = blockIdx.x * blockDim.x + threadIdx.x;
    int w = gtid >> 5;
    int lane = gtid & 31;
    if (w >= B) return;

    int r = it[w];
    int beg = d_rowptr[r], end = d_rowptr[r + 1];
    float2 acc = make_float2(0.f, 0.f);
    for (int e = beg; e < end; e++) {
        int s = d_col[e];
        unsigned int hb = d_gh[(size_t)s * 32 + lane];
        float2 gs = __half22float2(*(__half2*)&hb);
        acc.x += gs.x;
        acc.y += gs.y;
    }
    float di = d_dinv[r];
    unsigned int hr = d_gh[(size_t)r * 32 + lane];
    float2 gr = __half22float2(*(__half2*)&hr);
    float2 item = make_float2(di * (acc.x + gr.x) + b2[lane * 2 + 0],
                              di * (acc.y + gr.y) + b2[lane * 2 + 1]);

    int uu = u[w];
    float2 uv = *(const float2*)(user_emb + (size_t)uu * DIM + lane * 2);
    float ss = uv.x * uv.x + uv.y * uv.y;
    #pragma unroll
    for (int o = 16; o; o >>= 1) ss += __shfl_xor_sync(0xffffffffu, ss, o);
    float sc = fminf(1.0f, 1.0f / fmaxf(sqrtf(ss), 1e-12f));

    float dot = (uv.x * sc) * item.x + (uv.y * sc) * item.y;
    #pragma unroll
    for (int o = 16; o; o >>= 1) dot += __shfl_xor_sync(0xffffffffu, dot, o);

    if (lane == 0) out[w] = 1.0f / (1.0f + expf(-dot));
}

// ---------------- launch ----------------------------------------------------
extern "C" void kernel_launch(void* const* d_in, const int* in_sizes, int n_in,
                              void* d_out, int out_size) {
    const int*   u          = (const int*)d_in[0];
    const int*   it         = (const int*)d_in[1];
    const int*   edges      = (const int*)d_in[2];
    const float* user_emb   = (const float*)d_in[3];
    const float* entity_emb = (const float*)d_in[4];
    const float* W1         = (const float*)d_in[5];
    const float* b1         = (const float*)d_in[6];
    const float* W2         = (const float*)d_in[7];
    const float* b2         = (const float*)d_in[8];
    float*       out        = (float*)d_out;

    int B = in_sizes[0];
    int E = in_sizes[2] / 2;
    int n = in_sizes[4] / DIM;
    if (n > NCAP) n = NCAP;
    if (E > ECAP) E = ECAP;

    const int* src = edges;
    const int* dst = edges + E;

    const int T = 256;

    // zero degree counters
    int n4 = (n + 3) / 4;
    zero_cnt_kernel<<<(n4 + T - 1) / T, T>>>(n4);

    // degree counts (int4)
    int e4 = (E + 3) / 4;
    count_deg_kernel<<<(e4 + T - 1) / T, T>>>(dst, E);

    // CSR build (scan_bsums folded into finalize; finalize computes dinv)
    int nb = (n + 1023) / 1024;
    scan_chunk_kernel<<<nb, 1024>>>(n);
    finalize_rowptr_kernel<<<nb, 1024>>>(n, E);

    // renorm + premultiply by dinv into fp16 table (needs dinv)
    renorm_premul_kernel<<<(n + 7) / 8, T>>>(entity_emb, n);

    fill_csr_kernel<<<(e4 + T - 1) / T, T>>>(src, dst, E);

    // layer-1 aggregation (fp16 gathers, premultiplied weights)
    aggregate1_kernel<<<(n + 7) / 8, T>>>(n);

    // persistent fused g = fp16(dinv*(relu(agg1@W1+b1)@W2)), cp.async prefetch
    cudaFuncSetAttribute(gemm_fused_kernel,
                         cudaFuncAttributeMaxDynamicSharedMemorySize,
                         FUSED_SMEM_BYTES);
    gemm_fused_kernel<<<GEMM_GRID, 256, FUSED_SMEM_BYTES>>>(W1, b1, W2, n);

    // restricted layer-2 aggregation fused with user dot + sigmoid
    final_kernel<<<(B + 7) / 8, T>>>(u, it, user_emb, b2, out, B);
}

// round 16
// speedup vs baseline: 1.0800x; 1.0800x over previous
#include <cuda_runtime.h>
#include <cuda_fp16.h>
#include <mma.h>
#include <math.h>

using namespace nvcuda;

// Problem constants (fixed by the dataset)
#define NCAP 100000
#define ECAP 1600000
#define DIM  64
#define HID  128

// ---------------- scratch (device globals; no runtime allocation) ----------
static __device__ __align__(128) int   d_cnt[NCAP];
static __device__ __align__(128) int   d_rowptr[NCAP + 1];
static __device__ __align__(128) int   d_cursor[NCAP];
static __device__ __align__(128) int   d_bsum[256];
static __device__ __align__(128) int   d_col[ECAP];
static __device__ __align__(128) float d_dinv[NCAP];
static __device__ __align__(128) unsigned int d_xh[NCAP * 32];  // fp16x2 dinv*renorm(x)
static __device__ __align__(128) unsigned int d_a1h[NCAP * 32]; // fp16x2 Ahat(x)
static __device__ __align__(128) unsigned int d_gh[NCAP * 32];  // fp16x2 dinv*(relu(..)@W2)
static __device__ __align__(128) unsigned int d_w1h[64 * 128 / 2]; // fp16x2 W1
static __device__ __align__(128) unsigned int d_w2h[128 * 64 / 2]; // fp16x2 W2

// ---------------- zero degree counters + convert weights to fp16 -------------
__global__ void zero_cnt_wconv_kernel(const float* __restrict__ W1,
                                      const float* __restrict__ W2, int n4) {
    int i = blockIdx.x * blockDim.x + threadIdx.x;
    if (i < n4) *(int4*)&d_cnt[i * 4] = make_int4(0, 0, 0, 0);
    if (i < 4096) {               // W1: 64*128 = 8192 floats = 4096 half2
        float2 v = *(const float2*)&W1[i * 2];
        __half2 h = __floats2half2_rn(v.x, v.y);
        d_w1h[i] = *(unsigned int*)&h;
    } else if (i < 8192) {        // W2: 128*64
        int j = i - 4096;
        float2 v = *(const float2*)&W2[j * 2];
        __half2 h = __floats2half2_rn(v.x, v.y);
        d_w2h[j] = *(unsigned int*)&h;
    }
}

// ---------------- degree counting (int4) -------------------------------------
__global__ void count_deg_kernel(const int* __restrict__ dst, int E) {
    int i = blockIdx.x * blockDim.x + threadIdx.x;
    int e = i * 4;
    if (e + 3 < E) {
        int4 d = *(const int4*)(dst + e);
        atomicAdd(&d_cnt[d.x], 1);
        atomicAdd(&d_cnt[d.y], 1);
        atomicAdd(&d_cnt[d.z], 1);
        atomicAdd(&d_cnt[d.w], 1);
    } else {
        for (; e < E; e++) atomicAdd(&d_cnt[dst[e]], 1);
    }
}

// ---------------- prefix sum (chunked) ---------------------------------------
__global__ void scan_chunk_kernel(int n) {
    __shared__ int s[1024];
    int t = threadIdx.x;
    int i = blockIdx.x * 1024 + t;
    int v = (i < n) ? d_cnt[i] : 0;
    s[t] = v;
    __syncthreads();
    for (int off = 1; off < 1024; off <<= 1) {
        int add = (t >= off) ? s[t - off] : 0;
        __syncthreads();
        s[t] += add;
        __syncthreads();
    }
    if (i < n) d_rowptr[i] = s[t] - v;   // chunk-local exclusive
    if (t == 1023) d_bsum[blockIdx.x] = s[1023];
}

// finalize with inline bsum prefix: block c adds sum(d_bsum[0..c))
__global__ void finalize_rowptr_kernel(int n, int Etot) {
    __shared__ int s_off;
    int c = blockIdx.x, t = threadIdx.x;
    if (t < 32) {
        int s = 0;
        for (int j = t; j < c; j += 32) s += d_bsum[j];
        #pragma unroll
        for (int o = 16; o; o >>= 1) s += __shfl_xor_sync(0xffffffffu, s, o);
        if (t == 0) s_off = s;
    }
    __syncthreads();
    int i = c * 1024 + t;
    if (i < n) {
        int rp = d_rowptr[i] + s_off;
        d_rowptr[i] = rp;
        d_cursor[i] = rp;
        float deg = (float)(d_cnt[i] + 1);   // +1 self loop
        d_dinv[i] = rsqrtf(deg);
    }
    if (i == 0) d_rowptr[n] = Etot;
}

__global__ void fill_csr_kernel(const int* __restrict__ src,
                                const int* __restrict__ dst, int E) {
    int i = blockIdx.x * blockDim.x + threadIdx.x;
    int e = i * 4;
    if (e + 3 < E) {
        int4 d = *(const int4*)(dst + e);
        int4 s = *(const int4*)(src + e);
        d_col[atomicAdd(&d_cursor[d.x], 1)] = s.x;
        d_col[atomicAdd(&d_cursor[d.y], 1)] = s.y;
        d_col[atomicAdd(&d_cursor[d.z], 1)] = s.z;
        d_col[atomicAdd(&d_cursor[d.w], 1)] = s.w;
    } else {
        for (; e < E; e++) {
            int p = atomicAdd(&d_cursor[dst[e]], 1);
            d_col[p] = src[e];
        }
    }
}

// ---------------- renorm + premultiply by dinv, store fp16x2 -----------------
__global__ void renorm_premul_kernel(const float* __restrict__ emb, int n) {
    int gtid = blockIdx.x * blockDim.x + threadIdx.x;
    int row = gtid >> 5;
    int lane = gtid & 31;
    if (row >= n) return;
    float2 v = *(const float2*)(emb + (size_t)row * DIM + lane * 2);
    float ss = v.x * v.x + v.y * v.y;
    #pragma unroll
    for (int o = 16; o; o >>= 1) ss += __shfl_xor_sync(0xffffffffu, ss, o);
    float nrm = sqrtf(ss);
    float sc = fminf(1.0f, 1.0f / fmaxf(nrm, 1e-12f)) * d_dinv[row];
    __half2 h = __floats2half2_rn(v.x * sc, v.y * sc);
    d_xh[row * 32 + lane] = *(unsigned int*)&h;
}

// ---------------- aggregation: A = Ahat(x), fp32 accum -> fp16 out -----------
__global__ void aggregate1_kernel(int n) {
    int gtid = blockIdx.x * blockDim.x + threadIdx.x;
    int r = gtid >> 5;
    int lane = gtid & 31;
    if (r >= n) return;
    int beg = d_rowptr[r], end = d_rowptr[r + 1];
    float2 acc = make_float2(0.f, 0.f);
    for (int e = beg; e < end; e++) {
        int s = d_col[e];
        unsigned int hb = d_xh[s * 32 + lane];
        float2 xs = __half22float2(*(__half2*)&hb);
        acc.x += xs.x;
        acc.y += xs.y;
    }
    unsigned int hr = d_xh[r * 32 + lane];
    float2 self = __half22float2(*(__half2*)&hr);
    float di = d_dinv[r];
    __half2 h = __floats2half2_rn(di * (acc.x + self.x),
                                  di * (acc.y + self.y));
    d_a1h[r * 32 + lane] = *(unsigned int*)&h;
}

// ---------------- tensor-core fused GEMM1+GEMM2 (wmma fp16, f32 accum) -------
// Per block: 128 rows. Warp w owns row-tile w (16 rows) for BOTH stages:
//   stage 1: H[16,128] = relu(A[16,64] @ W1[64,128] + b1)   (4 k-steps)
//   stage 2: G[16,64]  = fp16(dinv * (H[16,128] @ W2[128,64]))  (8 k-steps)
// Epilogues go through a per-warp 16x16 f32 scratch (known row-major layout).
#define AH_LD 72        // halfs per A row (64 + 8 pad)
#define HH_LD 136       // halfs per H row (128 + 8 pad)
#define TC_SMEM_BYTES (8 * 256 * 4 /*scratch*/ + (64 * 128 + 128 * 64 + 128 * AH_LD + 128 * HH_LD) * 2)

__global__ __launch_bounds__(256, 2)
void gemm_tc_kernel(const float* __restrict__ b1, int M) {
    extern __shared__ char smem_raw[];
    float*  scratch = (float*)smem_raw;               // [8][256] per-warp
    __half* sW1 = (__half*)(scratch + 8 * 256);       // [64][128] row-major
    __half* sW2 = sW1 + 64 * 128;                     // [128][64] row-major
    __half* sA  = sW2 + 128 * 64;                     // [128][AH_LD]
    __half* sH  = sA + 128 * AH_LD;                   // [128][HH_LD]

    const int tid = threadIdx.x;
    const int w = tid >> 5, lane = tid & 31;
    const int rowBase = blockIdx.x * 128;

    // --- stage weights into smem (1024 uint4 each pair) ---
    for (int t = tid; t < 1024; t += 256) {
        ((uint4*)sW1)[t] = ((const uint4*)d_w1h)[t];
        ((uint4*)sW2)[t] = ((const uint4*)d_w2h)[t];
    }
    // --- load A tile (fp16, 8 uint4 per row) ---
    for (int t = tid; t < 1024; t += 256) {
        int r = t >> 3, q = t & 7;
        int gr = rowBase + r;
        uint4 v = make_uint4(0u, 0u, 0u, 0u);
        if (gr < M) v = *(const uint4*)&d_a1h[(size_t)gr * 32 + q * 4];
        *(uint4*)&sA[r * AH_LD + q * 8] = v;
    }
    __syncthreads();

    float* sc = scratch + w * 256;
    const int rl = lane >> 1, c8 = (lane & 1) * 8;

    // ==== stage 1: 8 col-tiles of 16, K = 64 (4 k-steps) ====
    wmma::fragment<wmma::accumulator, 16, 16, 16, float> c1[8];
    #pragma unroll
    for (int j = 0; j < 8; j++) wmma::fill_fragment(c1[j], 0.0f);
    #pragma unroll
    for (int k = 0; k < 4; k++) {
        wmma::fragment<wmma::matrix_a, 16, 16, 16, __half, wmma::row_major> af;
        wmma::load_matrix_sync(af, sA + (w * 16) * AH_LD + k * 16, AH_LD);
        #pragma unroll
        for (int j = 0; j < 8; j++) {
            wmma::fragment<wmma::matrix_b, 16, 16, 16, __half, wmma::row_major> bf;
            wmma::load_matrix_sync(bf, sW1 + (k * 16) * 128 + j * 16, 128);
            wmma::mma_sync(c1[j], af, bf, c1[j]);
        }
    }
    // epilogue 1: scratch roundtrip -> bias + relu -> fp16 H
    #pragma unroll
    for (int j = 0; j < 8; j++) {
        wmma::store_matrix_sync(sc, c1[j], 16, wmma::mem_row_major);
        __syncwarp();
        int col = j * 16 + c8;
        uint4 o;
        unsigned* op = (unsigned*)&o;
        #pragma unroll
        for (int q = 0; q < 4; q++) {
            float v0 = sc[rl * 16 + c8 + 2 * q]     + b1[col + 2 * q];
            float v1 = sc[rl * 16 + c8 + 2 * q + 1] + b1[col + 2 * q + 1];
            __half2 h = __floats2half2_rn(fmaxf(v0, 0.f), fmaxf(v1, 0.f));
            op[q] = *(unsigned*)&h;
        }
        *(uint4*)&sH[(w * 16 + rl) * HH_LD + col] = o;
        __syncwarp();
    }
    // warp w consumes only its own H rows -> no block-wide sync needed

    // ==== stage 2: 4 col-tiles of 16, K = 128 (8 k-steps) ====
    wmma::fragment<wmma::accumulator, 16, 16, 16, float> c2[4];
    #pragma unroll
    for (int j = 0; j < 4; j++) wmma::fill_fragment(c2[j], 0.0f);
    #pragma unroll
    for (int k = 0; k < 8; k++) {
        wmma::fragment<wmma::matrix_a, 16, 16, 16, __half, wmma::row_major> af;
        wmma::load_matrix_sync(af, sH + (w * 16) * HH_LD + k * 16, HH_LD);
        #pragma unroll
        for (int j = 0; j < 4; j++) {
            wmma::fragment<wmma::matrix_b, 16, 16, 16, __half, wmma::row_major> bf;
            wmma::load_matrix_sync(bf, sW2 + (k * 16) * 64 + j * 16, 64);
            wmma::mma_sync(c2[j], af, bf, c2[j]);
        }
    }
    // epilogue 2: scratch roundtrip -> dinv scale -> fp16 d_gh
    #pragma unroll
    for (int j = 0; j < 4; j++) {
        wmma::store_matrix_sync(sc, c2[j], 16, wmma::mem_row_major);
        __syncwarp();
        int gr = rowBase + w * 16 + rl;
        if (gr < M) {
            float dv = d_dinv[gr];
            uint4 o;
            unsigned* op = (unsigned*)&o;
            #pragma unroll
            for (int q = 0; q < 4; q++) {
                float v0 = sc[rl * 16 + c8 + 2 * q]     * dv;
                float v1 = sc[rl * 16 + c8 + 2 * q + 1] * dv;
                __half2 h = __floats2half2_rn(v0, v1);
                op[q] = *(unsigned*)&h;
            }
            *(uint4*)&d_gh[(size_t)gr * 32 + (j * 16 + c8) / 2] = o;
        }
        __syncwarp();
    }
}

// ---------------- final: agg2 restricted to batch items + user dot ----------
// d_gh holds g' = fp16(dinv*g):  item = dinv[r]*(sum g'[s] + g'[r]) + b2
__global__ void final_kernel(const int* __restrict__ u,
                             const int* __restrict__ it,
                             const float* __restrict__ user_emb,
                             const float* __restrict__ b2,
                             float* __restrict__ out, int B) {
    int gtid = blockIdx.x * blockDim.x + threadIdx.x;
    int w = gtid >> 5;
    int lane = gtid & 31;
    if (w >= B) return;

    int r = it[w];
    int beg = d_rowptr[r], end = d_rowptr[r + 1];
    float2 acc = make_float2(0.f, 0.f);
    for (int e = beg; e < end; e++) {
        int s = d_col[e];
        unsigned int hb = d_gh[(size_t)s * 32 + lane];
        float2 gs = __half22float2(*(__half2*)&hb);
        acc.x += gs.x;
        acc.y += gs.y;
    }
    float di = d_dinv[r];
    unsigned int hr = d_gh[(size_t)r * 32 + lane];
    float2 gr = __half22float2(*(__half2*)&hr);
    float2 item = make_float2(di * (acc.x + gr.x) + b2[lane * 2 + 0],
                              di * (acc.y + gr.y) + b2[lane * 2 + 1]);

    int uu = u[w];
    float2 uv = *(const float2*)(user_emb + (size_t)uu * DIM + lane * 2);
    float ss = uv.x * uv.x + uv.y * uv.y;
    #pragma unroll
    for (int o = 16; o; o >>= 1) ss += __shfl_xor_sync(0xffffffffu, ss, o);
    float sc = fminf(1.0f, 1.0f / fmaxf(sqrtf(ss), 1e-12f));

    float dot = (uv.x * sc) * item.x + (uv.y * sc) * item.y;
    #pragma unroll
    for (int o = 16; o; o >>= 1) dot += __shfl_xor_sync(0xffffffffu, dot, o);

    if (lane == 0) out[w] = 1.0f / (1.0f + expf(-dot));
}

// ---------------- launch ----------------------------------------------------
extern "C" void kernel_launch(void* const* d_in, const int* in_sizes, int n_in,
                              void* d_out, int out_size) {
    const int*   u          = (const int*)d_in[0];
    const int*   it         = (const int*)d_in[1];
    const int*   edges      = (const int*)d_in[2];
    const float* user_emb   = (const float*)d_in[3];
    const float* entity_emb = (const float*)d_in[4];
    const float* W1         = (const float*)d_in[5];
    const float* b1         = (const float*)d_in[6];
    const float* W2         = (const float*)d_in[7];
    const float* b2         = (const float*)d_in[8];
    float*       out        = (float*)d_out;

    int B = in_sizes[0];
    int E = in_sizes[2] / 2;
    int n = in_sizes[4] / DIM;
    if (n > NCAP) n = NCAP;
    if (E > ECAP) E = ECAP;

    const int* src = edges;
    const int* dst = edges + E;

    const int T = 256;

    // zero degree counters + convert W1/W2 to fp16 (one kernel)
    int n4 = (n + 3) / 4;
    zero_cnt_wconv_kernel<<<(n4 + T - 1) / T, T>>>(W1, W2, n4);

    // degree counts (int4)
    int e4 = (E + 3) / 4;
    count_deg_kernel<<<(e4 + T - 1) / T, T>>>(dst, E);

    // CSR build (scan_bsums folded into finalize; finalize computes dinv)
    int nb = (n + 1023) / 1024;
    scan_chunk_kernel<<<nb, 1024>>>(n);
    finalize_rowptr_kernel<<<nb, 1024>>>(n, E);

    // renorm + premultiply by dinv into fp16 table (needs dinv)
    renorm_premul_kernel<<<(n + 7) / 8, T>>>(entity_emb, n);

    fill_csr_kernel<<<(e4 + T - 1) / T, T>>>(src, dst, E);

    // layer-1 aggregation (fp16 gathers, fp32 accum, fp16 out)
    aggregate1_kernel<<<(n + 7) / 8, T>>>(n);

    // tensor-core fused g = fp16(dinv*(relu(A@W1+b1)@W2))
    cudaFuncSetAttribute(gemm_tc_kernel,
                         cudaFuncAttributeMaxDynamicSharedMemorySize,
                         TC_SMEM_BYTES);
    int gblocks = (n + 127) / 128;
    gemm_tc_kernel<<<gblocks, 256, TC_SMEM_BYTES>>>(b1, n);

    // restricted layer-2 aggregation fused with user dot + sigmoid
    final_kernel<<<(B + 7) / 8, T>>>(u, it, user_emb, b2, out, B);
}

// round 17
// speedup vs baseline: 1.1033x; 1.0216x over previous
#include <cuda_runtime.h>
#include <cuda_fp16.h>
#include <mma.h>
#include <math.h>

using namespace nvcuda;

// Problem constants (fixed by the dataset)
#define NCAP 100000
#define ECAP 1600000
#define DIM  64
#define HID  128

// ---------------- scratch (device globals; no runtime allocation) ----------
static __device__ __align__(128) int   d_cnt[NCAP];          // zero at launch entry (static init + self-reset)
static __device__ __align__(128) int   d_rowptr[NCAP + 1];
static __device__ __align__(128) int   d_cursor[NCAP];
static __device__ __align__(128) int   d_bstate[256];        // lookback aggregates (-1 = not ready)
static __device__ __align__(128) int   d_col[ECAP];
static __device__ __align__(128) float d_dinv[NCAP];
static __device__ __align__(128) unsigned int d_xh[NCAP * 32];  // fp16x2 dinv*renorm(x)
static __device__ __align__(128) unsigned int d_a1h[NCAP * 32]; // fp16x2 Ahat(x)
static __device__ __align__(128) unsigned int d_gh[NCAP * 32];  // fp16x2 dinv*(relu(..)@W2)
static __device__ __align__(128) unsigned int d_w1h[64 * 128 / 2]; // fp16x2 W1
static __device__ __align__(128) unsigned int d_w2h[128 * 64 / 2]; // fp16x2 W2

// ---------------- degree counting (int4) + bstate init + weight conv --------
__global__ void count_deg_kernel(const int* __restrict__ dst, int E,
                                 const float* __restrict__ W1,
                                 const float* __restrict__ W2, int nb) {
    int i = blockIdx.x * blockDim.x + threadIdx.x;
    if (i < nb) d_bstate[i] = -1;                    // reset lookback states
    if (i < 4096) {                                  // W1: 8192 floats = 4096 half2
        float2 v = *(const float2*)&W1[i * 2];
        __half2 h = __floats2half2_rn(v.x, v.y);
        d_w1h[i] = *(unsigned int*)&h;
    } else if (i < 8192) {                           // W2: 128*64
        int j = i - 4096;
        float2 v = *(const float2*)&W2[j * 2];
        __half2 h = __floats2half2_rn(v.x, v.y);
        d_w2h[j] = *(unsigned int*)&h;
    }
    int e = i * 4;
    if (e + 3 < E) {
        int4 d = *(const int4*)(dst + e);
        atomicAdd(&d_cnt[d.x], 1);
        atomicAdd(&d_cnt[d.y], 1);
        atomicAdd(&d_cnt[d.z], 1);
        atomicAdd(&d_cnt[d.w], 1);
    } else {
        for (; e < E; e++) atomicAdd(&d_cnt[dst[e]], 1);
    }
}

// ---------------- single-pass scan + finalize (decoupled lookback) -----------
// Block b scans its 1024-chunk of d_cnt (warp-shfl, 2 barriers), publishes its
// aggregate, warp 0 spin-sums predececessor aggregates (all blocks resident:
// nb=98 <= 152 SMs -> no deadlock). Then writes rowptr/cursor/dinv and zeroes
// d_cnt for the next graph replay.
__global__ void scan_fused_kernel(int n, int Etot) {
    __shared__ int wsum[32];
    __shared__ int s_off;
    const int t = threadIdx.x, b = blockIdx.x;
    const int lane = t & 31, w = t >> 5;
    const int i = b * 1024 + t;
    int v = (i < n) ? d_cnt[i] : 0;

    // warp inclusive scan
    int s = v;
    #pragma unroll
    for (int o = 1; o < 32; o <<= 1) {
        int u = __shfl_up_sync(0xffffffffu, s, o);
        if (lane >= o) s += u;
    }
    if (lane == 31) wsum[w] = s;
    __syncthreads();
    if (w == 0) {
        int ws = wsum[lane];
        #pragma unroll
        for (int o = 1; o < 32; o <<= 1) {
            int u = __shfl_up_sync(0xffffffffu, ws, o);
            if (lane >= o) ws += u;
        }
        wsum[lane] = ws;
    }
    __syncthreads();
    int incl = s + (w > 0 ? wsum[w - 1] : 0);
    int total = wsum[31];

    // publish aggregate (single word; atomicity = ordering)
    if (t == 0) atomicExch(&d_bstate[b], total);

    // lookback: warp 0 sums all predecessor aggregates
    if (t < 32) {
        int acc = 0;
        for (int j = lane; j < b; j += 32) {
            int x;
            do { x = atomicAdd(&d_bstate[j], 0); } while (x < 0);
            acc += x;
        }
        #pragma unroll
        for (int o = 16; o; o >>= 1) acc += __shfl_xor_sync(0xffffffffu, acc, o);
        if (lane == 0) s_off = acc;
    }
    __syncthreads();

    if (i < n) {
        int rp = incl - v + s_off;
        d_rowptr[i] = rp;
        d_cursor[i] = rp;
        d_dinv[i] = rsqrtf((float)(v + 1));   // +1 self loop
        d_cnt[i] = 0;                         // reset for next replay
    }
    if (i == 0) d_rowptr[n] = Etot;
}

__global__ void fill_csr_kernel(const int* __restrict__ src,
                                const int* __restrict__ dst, int E) {
    int i = blockIdx.x * blockDim.x + threadIdx.x;
    int e = i * 4;
    if (e + 3 < E) {
        int4 d = *(const int4*)(dst + e);
        int4 s = *(const int4*)(src + e);
        d_col[atomicAdd(&d_cursor[d.x], 1)] = s.x;
        d_col[atomicAdd(&d_cursor[d.y], 1)] = s.y;
        d_col[atomicAdd(&d_cursor[d.z], 1)] = s.z;
        d_col[atomicAdd(&d_cursor[d.w], 1)] = s.w;
    } else {
        for (; e < E; e++) {
            int p = atomicAdd(&d_cursor[dst[e]], 1);
            d_col[p] = src[e];
        }
    }
}

// ---------------- renorm + premultiply by dinv, store fp16x2 -----------------
__global__ void renorm_premul_kernel(const float* __restrict__ emb, int n) {
    int gtid = blockIdx.x * blockDim.x + threadIdx.x;
    int row = gtid >> 5;
    int lane = gtid & 31;
    if (row >= n) return;
    float2 v = *(const float2*)(emb + (size_t)row * DIM + lane * 2);
    float ss = v.x * v.x + v.y * v.y;
    #pragma unroll
    for (int o = 16; o; o >>= 1) ss += __shfl_xor_sync(0xffffffffu, ss, o);
    float nrm = sqrtf(ss);
    float sc = fminf(1.0f, 1.0f / fmaxf(nrm, 1e-12f)) * d_dinv[row];
    __half2 h = __floats2half2_rn(v.x * sc, v.y * sc);
    d_xh[row * 32 + lane] = *(unsigned int*)&h;
}

// ---------------- aggregation: A = Ahat(x), fp32 accum -> fp16 out -----------
__global__ void aggregate1_kernel(int n) {
    int gtid = blockIdx.x * blockDim.x + threadIdx.x;
    int r = gtid >> 5;
    int lane = gtid & 31;
    if (r >= n) return;
    int beg = d_rowptr[r], end = d_rowptr[r + 1];
    float2 acc = make_float2(0.f, 0.f);
    for (int e = beg; e < end; e++) {
        int s = d_col[e];
        unsigned int hb = d_xh[s * 32 + lane];
        float2 xs = __half22float2(*(__half2*)&hb);
        acc.x += xs.x;
        acc.y += xs.y;
    }
    unsigned int hr = d_xh[r * 32 + lane];
    float2 self = __half22float2(*(__half2*)&hr);
    float di = d_dinv[r];
    __half2 h = __floats2half2_rn(di * (acc.x + self.x),
                                  di * (acc.y + self.y));
    d_a1h[r * 32 + lane] = *(unsigned int*)&h;
}

// ---------------- tensor-core fused GEMM1+GEMM2 (wmma fp16, f32 accum) -------
// Per block: 128 rows. Warp w owns row-tile w (16 rows) for BOTH stages:
//   stage 1: H[16,128] = relu(A[16,64] @ W1[64,128] + b1)   (4 k-steps)
//   stage 2: G[16,64]  = fp16(dinv * (H[16,128] @ W2[128,64]))  (8 k-steps)
// Epilogues go through a per-warp 16x16 f32 scratch (known row-major layout).
#define AH_LD 72        // halfs per A row (64 + 8 pad)
#define HH_LD 136       // halfs per H row (128 + 8 pad)
#define TC_SMEM_BYTES (8 * 256 * 4 /*scratch*/ + (64 * 128 + 128 * 64 + 128 * AH_LD + 128 * HH_LD) * 2)

__global__ __launch_bounds__(256, 2)
void gemm_tc_kernel(const float* __restrict__ b1, int M) {
    extern __shared__ char smem_raw[];
    float*  scratch = (float*)smem_raw;               // [8][256] per-warp
    __half* sW1 = (__half*)(scratch + 8 * 256);       // [64][128] row-major
    __half* sW2 = sW1 + 64 * 128;                     // [128][64] row-major
    __half* sA  = sW2 + 128 * 64;                     // [128][AH_LD]
    __half* sH  = sA + 128 * AH_LD;                   // [128][HH_LD]

    const int tid = threadIdx.x;
    const int w = tid >> 5, lane = tid & 31;
    const int rowBase = blockIdx.x * 128;

    // --- stage weights into smem (1024 uint4 each pair) ---
    for (int t = tid; t < 1024; t += 256) {
        ((uint4*)sW1)[t] = ((const uint4*)d_w1h)[t];
        ((uint4*)sW2)[t] = ((const uint4*)d_w2h)[t];
    }
    // --- load A tile (fp16, 8 uint4 per row) ---
    for (int t = tid; t < 1024; t += 256) {
        int r = t >> 3, q = t & 7;
        int gr = rowBase + r;
        uint4 v = make_uint4(0u, 0u, 0u, 0u);
        if (gr < M) v = *(const uint4*)&d_a1h[(size_t)gr * 32 + q * 4];
        *(uint4*)&sA[r * AH_LD + q * 8] = v;
    }
    __syncthreads();

    float* sc = scratch + w * 256;
    const int rl = lane >> 1, c8 = (lane & 1) * 8;

    // ==== stage 1: 8 col-tiles of 16, K = 64 (4 k-steps) ====
    wmma::fragment<wmma::accumulator, 16, 16, 16, float> c1[8];
    #pragma unroll
    for (int j = 0; j < 8; j++) wmma::fill_fragment(c1[j], 0.0f);
    #pragma unroll
    for (int k = 0; k < 4; k++) {
        wmma::fragment<wmma::matrix_a, 16, 16, 16, __half, wmma::row_major> af;
        wmma::load_matrix_sync(af, sA + (w * 16) * AH_LD + k * 16, AH_LD);
        #pragma unroll
        for (int j = 0; j < 8; j++) {
            wmma::fragment<wmma::matrix_b, 16, 16, 16, __half, wmma::row_major> bf;
            wmma::load_matrix_sync(bf, sW1 + (k * 16) * 128 + j * 16, 128);
            wmma::mma_sync(c1[j], af, bf, c1[j]);
        }
    }
    // epilogue 1: scratch roundtrip -> bias + relu -> fp16 H
    #pragma unroll
    for (int j = 0; j < 8; j++) {
        wmma::store_matrix_sync(sc, c1[j], 16, wmma::mem_row_major);
        __syncwarp();
        int col = j * 16 + c8;
        uint4 o;
        unsigned* op = (unsigned*)&o;
        #pragma unroll
        for (int q = 0; q < 4; q++) {
            float v0 = sc[rl * 16 + c8 + 2 * q]     + b1[col + 2 * q];
            float v1 = sc[rl * 16 + c8 + 2 * q + 1] + b1[col + 2 * q + 1];
            __half2 h = __floats2half2_rn(fmaxf(v0, 0.f), fmaxf(v1, 0.f));
            op[q] = *(unsigned*)&h;
        }
        *(uint4*)&sH[(w * 16 + rl) * HH_LD + col] = o;
        __syncwarp();
    }
    // warp w consumes only its own H rows -> no block-wide sync needed

    // ==== stage 2: 4 col-tiles of 16, K = 128 (8 k-steps) ====
    wmma::fragment<wmma::accumulator, 16, 16, 16, float> c2[4];
    #pragma unroll
    for (int j = 0; j < 4; j++) wmma::fill_fragment(c2[j], 0.0f);
    #pragma unroll
    for (int k = 0; k < 8; k++) {
        wmma::fragment<wmma::matrix_a, 16, 16, 16, __half, wmma::row_major> af;
        wmma::load_matrix_sync(af, sH + (w * 16) * HH_LD + k * 16, HH_LD);
        #pragma unroll
        for (int j = 0; j < 4; j++) {
            wmma::fragment<wmma::matrix_b, 16, 16, 16, __half, wmma::row_major> bf;
            wmma::load_matrix_sync(bf, sW2 + (k * 16) * 64 + j * 16, 64);
            wmma::mma_sync(c2[j], af, bf, c2[j]);
        }
    }
    // epilogue 2: scratch roundtrip -> dinv scale -> fp16 d_gh
    #pragma unroll
    for (int j = 0; j < 4; j++) {
        wmma::store_matrix_sync(sc, c2[j], 16, wmma::mem_row_major);
        __syncwarp();
        int gr = rowBase + w * 16 + rl;
        if (gr < M) {
            float dv = d_dinv[gr];
            uint4 o;
            unsigned* op = (unsigned*)&o;
            #pragma unroll
            for (int q = 0; q < 4; q++) {
                float v0 = sc[rl * 16 + c8 + 2 * q]     * dv;
                float v1 = sc[rl * 16 + c8 + 2 * q + 1] * dv;
                __half2 h = __floats2half2_rn(v0, v1);
                op[q] = *(unsigned*)&h;
            }
            *(uint4*)&d_gh[(size_t)gr * 32 + (j * 16 + c8) / 2] = o;
        }
        __syncwarp();
    }
}

// ---------------- final: agg2 restricted to batch items + user dot ----------
// d_gh holds g' = fp16(dinv*g):  item = dinv[r]*(sum g'[s] + g'[r]) + b2
__global__ void final_kernel(const int* __restrict__ u,
                             const int* __restrict__ it,
                             const float* __restrict__ user_emb,
                             const float* __restrict__ b2,
                             float* __restrict__ out, int B) {
    int gtid = blockIdx.x * blockDim.x + threadIdx.x;
    int w = gtid >> 5;
    int lane = gtid & 31;
    if (w >= B) return;

    int r = it[w];
    int beg = d_rowptr[r], end = d_rowptr[r + 1];
    float2 acc = make_float2(0.f, 0.f);
    for (int e = beg; e < end; e++) {
        int s = d_col[e];
        unsigned int hb = d_gh[(size_t)s * 32 + lane];
        float2 gs = __half22float2(*(__half2*)&hb);
        acc.x += gs.x;
        acc.y += gs.y;
    }
    float di = d_dinv[r];
    unsigned int hr = d_gh[(size_t)r * 32 + lane];
    float2 gr = __half22float2(*(__half2*)&hr);
    float2 item = make_float2(di * (acc.x + gr.x) + b2[lane * 2 + 0],
                              di * (acc.y + gr.y) + b2[lane * 2 + 1]);

    int uu = u[w];
    float2 uv = *(const float2*)(user_emb + (size_t)uu * DIM + lane * 2);
    float ss = uv.x * uv.x + uv.y * uv.y;
    #pragma unroll
    for (int o = 16; o; o >>= 1) ss += __shfl_xor_sync(0xffffffffu, ss, o);
    float sc = fminf(1.0f, 1.0f / fmaxf(sqrtf(ss), 1e-12f));

    float dot = (uv.x * sc) * item.x + (uv.y * sc) * item.y;
    #pragma unroll
    for (int o = 16; o; o >>= 1) dot += __shfl_xor_sync(0xffffffffu, dot, o);

    if (lane == 0) out[w] = 1.0f / (1.0f + expf(-dot));
}

// ---------------- launch ----------------------------------------------------
extern "C" void kernel_launch(void* const* d_in, const int* in_sizes, int n_in,
                              void* d_out, int out_size) {
    const int*   u          = (const int*)d_in[0];
    const int*   it         = (const int*)d_in[1];
    const int*   edges      = (const int*)d_in[2];
    const float* user_emb   = (const float*)d_in[3];
    const float* entity_emb = (const float*)d_in[4];
    const float* W1         = (const float*)d_in[5];
    const float* b1         = (const float*)d_in[6];
    const float* W2         = (const float*)d_in[7];
    const float* b2         = (const float*)d_in[8];
    float*       out        = (float*)d_out;

    int B = in_sizes[0];
    int E = in_sizes[2] / 2;
    int n = in_sizes[4] / DIM;
    if (n > NCAP) n = NCAP;
    if (E > ECAP) E = ECAP;

    const int* src = edges;
    const int* dst = edges + E;

    const int T = 256;
    int nb = (n + 1023) / 1024;

    // degree counts (+ bstate reset, + fp16 weight conversion)
    // d_cnt is zero here: static init on first run, self-reset by scan_fused after.
    int e4 = (E + 3) / 4;
    count_deg_kernel<<<(e4 + T - 1) / T, T>>>(dst, E, W1, W2, nb);

    // single-pass scan + finalize (rowptr, cursor, dinv; zeroes cnt)
    scan_fused_kernel<<<nb, 1024>>>(n, E);

    // renorm + premultiply by dinv into fp16 table (needs dinv)
    renorm_premul_kernel<<<(n + 7) / 8, T>>>(entity_emb, n);

    fill_csr_kernel<<<(e4 + T - 1) / T, T>>>(src, dst, E);

    // layer-1 aggregation (fp16 gathers, fp32 accum, fp16 out)
    aggregate1_kernel<<<(n + 7) / 8, T>>>(n);

    // tensor-core fused g = fp16(dinv*(relu(A@W1+b1)@W2))
    cudaFuncSetAttribute(gemm_tc_kernel,
                         cudaFuncAttributeMaxDynamicSharedMemorySize,
                         TC_SMEM_BYTES);
    int gblocks = (n + 127) / 128;
    gemm_tc_kernel<<<gblocks, 256, TC_SMEM_BYTES>>>(b1, n);

    // restricted layer-2 aggregation fused with user dot + sigmoid
    final_kernel<<<(B + 7) / 8, T>>>(u, it, user_emb, b2, out, B);
}